// round 10
// baseline (speedup 1.0000x reference)
#include <cuda_runtime.h>
#include <cuda_bf16.h>
#include <cuda_fp16.h>

#define Nn  8
#define Cc  64
#define Hh  128
#define Ww  512
#define CoN 64
#define HW  (Hh * Ww)      // 65536
#define NOFF 18
#define SSTRH 72           // deform tile stride in HALFS: 144B, 16B-aligned
#define XSTR 136           // offset-conv x-tile stride (floats)

// Scratch: offsets, fp16 deform B-frags, tf32 offset B-frags.
__device__ float  g_off[(size_t)Nn * NOFF * HW];   // ~36 MB
__device__ uint2  g_wfragh[9 * 4 * 8 * 32];        // fp16 deform B frags [t][k4][ni8][lane]
__device__ float2 g_wofrag[72 * 3 * 32];           // offset B frags (tf32)

__device__ __forceinline__ unsigned f2tf32(float v) {
    unsigned u;
    asm("cvt.rna.tf32.f32 %0, %1;" : "=r"(u) : "f"(v));
    return u;
}

// ---------------------------------------------------------------------------
// Kernel 0a: deform B fragments for fp16 m16n8k16.
// B[k][o] = w_def[o][k-channel][tap]. Lane (gr=lane>>2, tc=lane&3):
//   b0 = (B[16ks+2tc][8ni+gr], B[16ks+2tc+1][...])
//   b1 = (B[16ks+2tc+8][...],  B[16ks+2tc+9][...])
// ---------------------------------------------------------------------------
__global__ void wfragh_kernel(const float* __restrict__ wdef) {
    int idx = blockIdx.x * 256 + threadIdx.x;
    if (idx >= 9 * 4 * 8 * 32) return;
    int lane = idx & 31;
    int ni   = (idx >> 5) & 7;
    int k    = (idx >> 8) & 3;
    int t    = idx >> 10;
    int gr = lane >> 2, tc = lane & 3;
    int o  = 8 * ni + gr;
    int k0 = 16 * k + 2 * tc;
    float w00 = wdef[(o * 64 + k0)     * 9 + t];
    float w01 = wdef[(o * 64 + k0 + 1) * 9 + t];
    float w10 = wdef[(o * 64 + k0 + 8) * 9 + t];
    float w11 = wdef[(o * 64 + k0 + 9) * 9 + t];
    half2 b0 = __floats2half2_rn(w00, w01);
    half2 b1 = __floats2half2_rn(w10, w11);
    uint2 u;
    u.x = *(unsigned*)&b0;
    u.y = *(unsigned*)&b1;
    g_wfragh[idx] = u;
}

// ---------------------------------------------------------------------------
// Kernel 0b: offset-conv B fragments (oc padded 18 -> 24), tf32.
// ---------------------------------------------------------------------------
__global__ void wofrag_kernel(const float* __restrict__ woff) {
    int idx = blockIdx.x * 256 + threadIdx.x;
    if (idx >= 72 * 3 * 32) return;
    int lane = idx & 31;
    int rem  = idx >> 5;
    int ni   = rem % 3;
    int ks   = rem / 3;
    int gr = lane >> 2, tc = lane & 3;
    int k0 = 8 * ks + tc;
    int oc = 8 * ni + gr;
    float b0 = (oc < 18) ? woff[oc * 576 + k0]     : 0.0f;
    float b1 = (oc < 18) ? woff[oc * 576 + k0 + 4] : 0.0f;
    g_wofrag[(ks * 3 + ni) * 32 + lane] =
        make_float2(__uint_as_float(f2tf32(b0)), __uint_as_float(f2tf32(b1)));
}

// ---------------------------------------------------------------------------
// Kernel 1: offset conv via tf32 MMA — Round-4 version verbatim.
// ---------------------------------------------------------------------------
__global__ void __launch_bounds__(128) offset_mma_kernel(
    const float* __restrict__ xin,
    const float* __restrict__ boff)
{
    __shared__ float sx[24 * XSTR];

    int tid  = threadIdx.x;
    int lane = tid & 31;
    int warp = tid >> 5;
    int gr   = lane >> 2;
    int tc   = lane & 3;

    int x0 = blockIdx.x * 128;
    int y  = blockIdx.y;
    int n  = blockIdx.z;

    float acc[2][3][4];
#pragma unroll
    for (int ni = 0; ni < 3; ni++) {
        int oc = 8 * ni + 2 * tc;
        float blo = (oc < 18)     ? __ldg(&boff[oc])     : 0.0f;
        float bhi = (oc + 1 < 18) ? __ldg(&boff[oc + 1]) : 0.0f;
#pragma unroll
        for (int mi = 0; mi < 2; mi++) {
            acc[mi][ni][0] = blo; acc[mi][ni][1] = bhi;
            acc[mi][ni][2] = blo; acc[mi][ni][3] = bhi;
        }
    }

    const float* xb = xin + (size_t)n * Cc * HW;

    for (int ch = 0; ch < 8; ch++) {
        __syncthreads();
        for (int idx = tid; idx < 3120; idx += 128) {
            int c   = idx / 390;
            int r   = idx - 390 * c;
            int i   = r / 130;
            int col = r - 130 * i;
            int yy = y + i - 1;
            int xx = x0 + col - 1;
            float v = 0.0f;
            if (yy >= 0 && yy < Hh && xx >= 0 && xx < Ww)
                v = xb[(size_t)(ch * 8 + c) * HW + yy * Ww + xx];
            sx[(c * 3 + i) * XSTR + col] = __uint_as_float(f2tf32(v));
        }
        __syncthreads();

#pragma unroll
        for (int kk = 0; kk < 9; kk++) {
            int kl = 8 * kk + tc;
            int c0 = kl / 9,  t0 = kl - 9 * c0;
            int i0 = t0 / 3,  j0 = t0 - 3 * i0;
            int kl2 = kl + 4;
            int c1 = kl2 / 9, t1 = kl2 - 9 * c1;
            int i1 = t1 / 3,  j1 = t1 - 3 * i1;
            int off0 = (c0 * 3 + i0) * XSTR + j0;
            int off1 = (c1 * 3 + i1) * XSTR + j1;

            const float2* wf = g_wofrag + (size_t)(ch * 9 + kk) * 96;
            float2 bfr[3];
#pragma unroll
            for (int ni = 0; ni < 3; ni++) bfr[ni] = __ldg(&wf[ni * 32 + lane]);

#pragma unroll
            for (int mi = 0; mi < 2; mi++) {
                int m = warp * 32 + mi * 16 + gr;
                unsigned a0 = __float_as_uint(sx[off0 + m]);
                unsigned a1 = __float_as_uint(sx[off0 + m + 8]);
                unsigned a2 = __float_as_uint(sx[off1 + m]);
                unsigned a3 = __float_as_uint(sx[off1 + m + 8]);
#pragma unroll
                for (int ni = 0; ni < 3; ni++) {
                    unsigned b0 = __float_as_uint(bfr[ni].x);
                    unsigned b1 = __float_as_uint(bfr[ni].y);
                    asm volatile(
                        "mma.sync.aligned.m16n8k8.row.col.f32.tf32.tf32.f32 "
                        "{%0,%1,%2,%3}, {%4,%5,%6,%7}, {%8,%9}, {%0,%1,%2,%3};"
                        : "+f"(acc[mi][ni][0]), "+f"(acc[mi][ni][1]),
                          "+f"(acc[mi][ni][2]), "+f"(acc[mi][ni][3])
                        : "r"(a0), "r"(a1), "r"(a2), "r"(a3),
                          "r"(b0), "r"(b1));
                }
            }
        }
    }

    size_t ob = (size_t)n * NOFF * HW + (size_t)y * Ww + x0;
#pragma unroll
    for (int ni = 0; ni < 3; ni++) {
        int oc = 8 * ni + 2 * tc;
#pragma unroll
        for (int mi = 0; mi < 2; mi++) {
            int pr = warp * 32 + mi * 16 + gr;
            if (oc < 18) {
                g_off[ob + (size_t)oc * HW + pr]     = acc[mi][ni][0];
                g_off[ob + (size_t)oc * HW + pr + 8] = acc[mi][ni][2];
            }
            if (oc + 1 < 18) {
                g_off[ob + (size_t)(oc + 1) * HW + pr]     = acc[mi][ni][1];
                g_off[ob + (size_t)(oc + 1) * HW + pr + 8] = acc[mi][ni][3];
            }
        }
    }
}

// ---------------------------------------------------------------------------
// Kernel 2: deformable conv, fp16 m16n8k16 MMA.
// Structure as Round 9 (och split across warps, double-buffered tile, one
// pair-barrier per tap), but: samples stored as fp16 (144B rows), A fragments
// via ldmatrix.x4, B fragments fp16 (quarter bytes), half the MMA count.
// ---------------------------------------------------------------------------
__global__ void __launch_bounds__(128, 7) deform_mma_kernel(
    const float* __restrict__ xin,
    const float* __restrict__ bdef,
    float* __restrict__ out)
{
    __shared__ __align__(16) __half sS[2][64 * SSTRH];   // 2 x 9216 B

    int tid  = threadIdx.x;
    int lane = tid & 31;
    int warp = tid >> 5;
    int g    = warp & 1;      // pixel group
    int h    = warp >> 1;     // channel half (gather) / och half (MMA)
    int gr   = lane >> 2;
    int tc   = lane & 3;

    int x0  = blockIdx.x * 64;
    int y   = blockIdx.y;
    int n   = blockIdx.z;
    int pxl = tid & 63;       // gather pixel within CTA
    int xg  = x0 + pxl;

    float acc[2][4][4];
#pragma unroll
    for (int ni = 0; ni < 4; ni++) {
        int ni_g = 4 * h + ni;
        float blo = __ldg(&bdef[8 * ni_g + 2 * tc]);
        float bhi = __ldg(&bdef[8 * ni_g + 2 * tc + 1]);
#pragma unroll
        for (int mi = 0; mi < 2; mi++) {
            acc[mi][ni][0] = blo; acc[mi][ni][1] = bhi;
            acc[mi][ni][2] = blo; acc[mi][ni][3] = bhi;
        }
    }

    const float* xb   = xin + (size_t)n * Cc * HW + (size_t)(h * 32) * HW;
    const float* offb = g_off + (size_t)n * NOFF * HW + (size_t)y * Ww + xg;

    // ldmatrix source address for this lane (row/col within warp's M=32 block)
    // lane i reads row (i&15) of the 16-row block, col-half (i>>4)*8 halfs.
    unsigned smem_u32[2];   // per buffer: base for (g, lane); k/mi offsets added below
#pragma unroll
    for (int b = 0; b < 2; b++) {
        const __half* p = &sS[b][(32 * g + (lane & 15)) * SSTRH + (lane >> 4) * 8];
        smem_u32[b] = (unsigned)__cvta_generic_to_shared(p);
    }

    // prefetch tap-0 offsets
    float dy = offb[0];
    float dx = offb[(size_t)HW];

    for (int t = 0; t < 9; t++) {
        int i = t / 3, j = t % 3;
        float py  = (float)(y + i - 1) + dy;
        float pxf = (float)(xg + j - 1) + dx;

        if (t < 8) {
            dy = offb[(size_t)(2 * t + 2) * HW];
            dx = offb[(size_t)(2 * t + 3) * HW];
        }

        float fy = floorf(py), fx = floorf(pxf);
        float wy1 = py - fy, wx1 = pxf - fx;
        float wy0 = 1.0f - wy1, wx0 = 1.0f - wx1;
        int iy0 = (int)fy, ix0 = (int)fx;
        int iy1 = iy0 + 1, ix1 = ix0 + 1;

        float gy0 = (iy0 >= 0 && iy0 < Hh) ? wy0 : 0.0f;
        float gy1 = (iy1 >= 0 && iy1 < Hh) ? wy1 : 0.0f;
        float gx0 = (ix0 >= 0 && ix0 < Ww) ? wx0 : 0.0f;
        float gx1 = (ix1 >= 0 && ix1 < Ww) ? wx1 : 0.0f;
        float c00 = gy0 * gx0, c01 = gy0 * gx1;
        float c10 = gy1 * gx0, c11 = gy1 * gx1;

        int yc0 = min(max(iy0, 0), Hh - 1), yc1 = min(max(iy1, 0), Hh - 1);
        int xc0 = min(max(ix0, 0), Ww - 1), xc1 = min(max(ix1, 0), Ww - 1);
        int o00 = yc0 * Ww + xc0, o01 = yc0 * Ww + xc1;
        int o10 = yc1 * Ww + xc0, o11 = yc1 * Ww + xc1;

        __half* buf = sS[t & 1];

        {   // gather 32 channels of pixel pxl -> fp16, 4 x STS.128
            uint4* srow = (uint4*)(buf + pxl * SSTRH + 32 * h);
            const float* p = xb;
#pragma unroll
            for (int q = 0; q < 4; q++) {
                float s[8];
#pragma unroll
                for (int e = 0; e < 8; e++) {
                    float a = c00 * p[o00];
                    a = fmaf(c01, p[o01], a);
                    a = fmaf(c10, p[o10], a);
                    a = fmaf(c11, p[o11], a);
                    s[e] = a;
                    p += HW;
                }
                half2 hv[4];
                hv[0] = __floats2half2_rn(s[0], s[1]);
                hv[1] = __floats2half2_rn(s[2], s[3]);
                hv[2] = __floats2half2_rn(s[4], s[5]);
                hv[3] = __floats2half2_rn(s[6], s[7]);
                srow[q] = *(uint4*)hv;
            }
        }

        // single pair barrier per tap: buf[t&1] quadrants written
        asm volatile("bar.sync %0, %1;" :: "r"(1 + g), "r"(64) : "memory");

        const uint2* wf = g_wfragh + (size_t)t * 4 * 8 * 32;
        unsigned sbase = smem_u32[t & 1];
#pragma unroll
        for (int k = 0; k < 4; k++) {
            unsigned a[2][4];
#pragma unroll
            for (int mi = 0; mi < 2; mi++) {
                unsigned addr = sbase + (unsigned)(mi * 16 * SSTRH + k * 16) * 2u;
                asm volatile(
                    "ldmatrix.sync.aligned.m8n8.x4.shared.b16 {%0,%1,%2,%3}, [%4];"
                    : "=r"(a[mi][0]), "=r"(a[mi][1]), "=r"(a[mi][2]), "=r"(a[mi][3])
                    : "r"(addr));
            }
#pragma unroll
            for (int ni = 0; ni < 4; ni++) {
                int ni_g = 4 * h + ni;
                uint2 b = __ldg(&wf[(k * 8 + ni_g) * 32 + lane]);
#pragma unroll
                for (int mi = 0; mi < 2; mi++) {
                    asm volatile(
                        "mma.sync.aligned.m16n8k16.row.col.f32.f16.f16.f32 "
                        "{%0,%1,%2,%3}, {%4,%5,%6,%7}, {%8,%9}, {%0,%1,%2,%3};"
                        : "+f"(acc[mi][ni][0]), "+f"(acc[mi][ni][1]),
                          "+f"(acc[mi][ni][2]), "+f"(acc[mi][ni][3])
                        : "r"(a[mi][0]), "r"(a[mi][1]), "r"(a[mi][2]), "r"(a[mi][3]),
                          "r"(b.x), "r"(b.y));
                }
            }
        }
    }

    // epilogue: warp writes its 32 px x 32 och
    size_t ob = (size_t)n * CoN * HW + (size_t)y * Ww + x0;
#pragma unroll
    for (int ni = 0; ni < 4; ni++) {
        int o = 8 * (4 * h + ni) + 2 * tc;
#pragma unroll
        for (int mi = 0; mi < 2; mi++) {
            int pr = 32 * g + mi * 16 + gr;
            out[ob + (size_t)o * HW + pr]           = acc[mi][ni][0];
            out[ob + (size_t)(o + 1) * HW + pr]     = acc[mi][ni][1];
            out[ob + (size_t)o * HW + pr + 8]       = acc[mi][ni][2];
            out[ob + (size_t)(o + 1) * HW + pr + 8] = acc[mi][ni][3];
        }
    }
}

// ---------------------------------------------------------------------------
extern "C" void kernel_launch(void* const* d_in, const int* in_sizes, int n_in,
                              void* d_out, int out_size)
{
    const float* x    = (const float*)d_in[0];
    const float* woff = (const float*)d_in[1];
    const float* boff = (const float*)d_in[2];
    const float* wdef = (const float*)d_in[3];
    const float* bdef = (const float*)d_in[4];
    float* out = (float*)d_out;

    wfragh_kernel<<<(9 * 4 * 8 * 32 + 255) / 256, 256>>>(wdef);
    wofrag_kernel<<<(72 * 3 * 32 + 255) / 256, 256>>>(woff);
    offset_mma_kernel<<<dim3(Ww / 128, Hh, Nn), 128>>>(x, boff);
    deform_mma_kernel<<<dim3(Ww / 64, Hh, Nn), 128>>>(x, bdef, out);
}